// round 1
// baseline (speedup 1.0000x reference)
#include <cuda_runtime.h>

// Folded filter: G[h*16+w] = (1/25) * sum over pool windows (i,j) covering (h,w) of W[i*6+j]
__device__ float g_filter[256];
__device__ float g_bias;

__global__ void build_filter_kernel(const float* __restrict__ W,
                                    const float* __restrict__ b) {
    int t = threadIdx.x;          // 0..255
    int h = t >> 4;
    int w = t & 15;
    float s = 0.0f;
    #pragma unroll
    for (int i = 0; i < 6; i++) {
        int top = i * 2;
        if (h >= top && h <= top + 4) {
            #pragma unroll
            for (int j = 0; j < 6; j++) {
                int left = j * 2;
                if (w >= left && w <= left + 4) s += W[i * 6 + j];
            }
        }
    }
    g_filter[t] = s * 0.04f;      // 1/25
    if (t == 0) g_bias = b[0];
}

// One warp per (b,c): 256 contiguous floats = 64 float4. Each lane handles 2 float4.
__global__ void __launch_bounds__(256)
pool_linear_kernel(const float4* __restrict__ x, float* __restrict__ out,
                   int n_rows) {
    __shared__ float4 gs[64];
    int tid = threadIdx.x;
    if (tid < 64) gs[tid] = reinterpret_cast<const float4*>(g_filter)[tid];
    __syncthreads();

    int gwarp = (blockIdx.x * blockDim.x + tid) >> 5;
    int lane  = tid & 31;
    if (gwarp >= n_rows) return;

    const float4* row = x + (size_t)gwarp * 64;
    float4 a0 = row[lane];
    float4 a1 = row[lane + 32];
    float4 g0 = gs[lane];
    float4 g1 = gs[lane + 32];

    float s = a0.x * g0.x + a0.y * g0.y + a0.z * g0.z + a0.w * g0.w
            + a1.x * g1.x + a1.y * g1.y + a1.z * g1.z + a1.w * g1.w;

    #pragma unroll
    for (int off = 16; off > 0; off >>= 1)
        s += __shfl_down_sync(0xffffffffu, s, off);

    if (lane == 0) out[gwarp] = s + g_bias;
}

extern "C" void kernel_launch(void* const* d_in, const int* in_sizes, int n_in,
                              void* d_out, int out_size) {
    const float* x = (const float*)d_in[0];   // [256, 512, 16, 16]
    const float* W = (const float*)d_in[1];   // [1, 36]
    const float* b = (const float*)d_in[2];   // [1]
    float* out = (float*)d_out;               // [256, 512]

    int n_rows = out_size;                    // B*C = 131072 rows of 256 floats

    build_filter_kernel<<<1, 256>>>(W, b);

    int threads = 256;                        // 8 warps/block
    int blocks = (n_rows * 32 + threads - 1) / threads;
    pool_linear_kernel<<<blocks, threads>>>(
        reinterpret_cast<const float4*>(x), out, n_rows);
}